// round 16
// baseline (speedup 1.0000x reference)
#include <cuda_runtime.h>
#include <cuda_bf16.h>
#include <cstdint>

#define NN 100000
#define NE 600000
#define NBLK 196   // ceil(NN/512) scan blocks

// ---------------- scratch (device globals; no allocation allowed) ----------
__device__ float    g_bufH[(size_t)NN * 128];
__device__ float    g_bufA[(size_t)NN * 128];
__device__ float    g_bufB[(size_t)NN * 128];
__device__ float    g_dinv[NN];
__device__ unsigned long long g_pack[NN];    // count<<40 | fixpoint(weight, 2^16)
__device__ int      g_rowptr[NN + 1];
__device__ int      g_cur[NN];
__device__ int2     g_edge[NE];              // {src, float-bits(ew)}
__device__ unsigned g_x0[32];
__device__ unsigned g_x1[32];
__device__ unsigned long long g_pub[NBLK];   // lookback: flag(bit32) | sum
__device__ __align__(16) __nv_bfloat16 g_wHi2[32 * 128];
__device__ __align__(16) __nv_bfloat16 g_wLo2[32 * 128];
__device__ __align__(16) __nv_bfloat16 g_wHi3[128 * 128];
__device__ __align__(16) __nv_bfloat16 g_wLo3[128 * 128];
__device__ __align__(16) __nv_bfloat16 g_wHi4[128 * 32];
__device__ __align__(16) __nv_bfloat16 g_wLo4[128 * 32];

// ======================= mma.sync helpers ===================================
__device__ __forceinline__ uint32_t smem_u32(const void* p) {
    uint32_t a;
    asm("{ .reg .u64 t; cvta.to.shared.u64 t, %1; cvt.u32.u64 %0, t; }"
        : "=r"(a) : "l"(p));
    return a;
}

__device__ __forceinline__ void ldmx2(uint32_t* r, uint32_t addr) {
    asm volatile("ldmatrix.sync.aligned.m8n8.x2.shared.b16 {%0,%1}, [%2];"
                 : "=r"(r[0]), "=r"(r[1]) : "r"(addr));
}

__device__ __forceinline__ void mma16816(float* c, const uint32_t* a, const uint32_t* b) {
    asm volatile(
        "mma.sync.aligned.m16n8k16.row.col.f32.bf16.bf16.f32 "
        "{%0,%1,%2,%3}, {%4,%5,%6,%7}, {%8,%9}, {%0,%1,%2,%3};"
        : "+f"(c[0]), "+f"(c[1]), "+f"(c[2]), "+f"(c[3])
        : "r"(a[0]), "r"(a[1]), "r"(a[2]), "r"(a[3]), "r"(b[0]), "r"(b[1]));
}

__device__ __forceinline__ void cvt2(float2 f, uint32_t& hi, uint32_t& lo) {
    __nv_bfloat162 h = __floats2bfloat162_rn(f.x, f.y);
    float2 hf = __bfloat1622float2(h);
    __nv_bfloat162 l = __floats2bfloat162_rn(f.x - hf.x, f.y - hf.y);
    hi = *(uint32_t*)&h;
    lo = *(uint32_t*)&l;
}

__device__ __forceinline__ void cvt_hilo(float x, unsigned short& h, unsigned short& l) {
    __nv_bfloat16 hb = __float2bfloat16(x);
    __nv_bfloat16 lb = __float2bfloat16(x - __bfloat162float(hb));
    h = __bfloat16_as_ushort(hb);
    l = __bfloat16_as_ushort(lb);
}

// ---------------- init + weight convert (one kernel) ------------------------
__global__ void k_wconv_init(const float* __restrict__ W2,
                             const float* __restrict__ W3,
                             const float* __restrict__ W4) {
    int i = blockIdx.x * 256 + threadIdx.x;
    if (i < NN) g_pack[i] = 65536ULL;   // self-loop weight 1.0 (2^16), count 0
    if (i < 32) { g_x0[i] = 0u; g_x1[i] = 0u; }
    if (i < NBLK) g_pub[i] = 0ULL;
    unsigned short h, l;
    if (i < 4096) {                                   // W2: K=32, N=128
        int n = i >> 5, k = i & 31;
        cvt_hilo(W2[k * 128 + n], h, l);
        g_wHi2[i] = __ushort_as_bfloat16(h);
        g_wLo2[i] = __ushort_as_bfloat16(l);
    } else if (i < 4096 + 16384) {                    // W3: K=128, N=128
        int j = i - 4096;
        int n = j >> 7, k = j & 127;
        cvt_hilo(W3[k * 128 + n], h, l);
        g_wHi3[j] = __ushort_as_bfloat16(h);
        g_wLo3[j] = __ushort_as_bfloat16(l);
    } else if (i < 4096 + 16384 + 4096) {             // W4: K=128, N=32
        int j = i - 20480;
        int n = j >> 7, k = j & 127;
        cvt_hilo(W4[k * 32 + n], h, l);
        g_wHi4[j] = __ushort_as_bfloat16(h);
        g_wLo4[j] = __ushort_as_bfloat16(l);
    }
}

// ---------------- degree: 4 edges/thread, ONE packed atomic per edge --------
__global__ void k_deg4(const int* __restrict__ dst, const float* __restrict__ ew) {
    int i = blockIdx.x * 256 + threadIdx.x;
    if (i < NE / 4) {
        int4   d = ((const int4*)dst)[i];
        float4 w = ((const float4*)ew)[i];
        const unsigned long long ONE = 1ULL << 40;
        atomicAdd(&g_pack[d.x], ONE + (unsigned long long)__float2uint_rn(w.x * 65536.0f));
        atomicAdd(&g_pack[d.y], ONE + (unsigned long long)__float2uint_rn(w.y * 65536.0f));
        atomicAdd(&g_pack[d.z], ONE + (unsigned long long)__float2uint_rn(w.z * 65536.0f));
        atomicAdd(&g_pack[d.w], ONE + (unsigned long long)__float2uint_rn(w.w * 65536.0f));
    }
}

// ---------------- single-kernel exclusive scan + dinv + x prescale ----------
__global__ void __launch_bounds__(512) k_scan(const float* __restrict__ x,
                                              float* __restrict__ xs) {
    __shared__ int s[512];
    __shared__ int spart[512];
    int tid = threadIdx.x, bid = blockIdx.x;
    int i = bid * 512 + tid;
    int v = 0;
    if (i < NN) {
        unsigned long long p = g_pack[i];
        v = (int)(p >> 40);
        float d = rsqrtf((float)(p & 0xFFFFFFFFFFULL) * (1.0f / 65536.0f));
        g_dinv[i] = d;
        float4 a = ((const float4*)x)[i * 2];
        float4 b = ((const float4*)x)[i * 2 + 1];
        a.x *= d; a.y *= d; a.z *= d; a.w *= d;
        b.x *= d; b.y *= d; b.z *= d; b.w *= d;
        ((float4*)xs)[i * 2]     = a;
        ((float4*)xs)[i * 2 + 1] = b;
    }
    s[tid] = v;
    __syncthreads();
#pragma unroll
    for (int off = 1; off < 512; off <<= 1) {
        int t = 0;
        if (tid >= off) t = s[tid - off];
        __syncthreads();
        if (tid >= off) s[tid] += t;
        __syncthreads();
    }
    if (tid == 511)
        atomicExch(&g_pub[bid], (1ULL << 32) | (unsigned long long)(unsigned)s[511]);

    int part = 0;
    for (int j = tid; j < bid; j += 512) {
        unsigned long long p;
        do { p = atomicAdd(&g_pub[j], 0ULL); } while ((p >> 32) == 0ULL);
        part += (int)(p & 0xffffffffULL);
    }
    spart[tid] = part;
    __syncthreads();
#pragma unroll
    for (int ssz = 256; ssz > 0; ssz >>= 1) {
        if (tid < ssz) spart[tid] += spart[tid + ssz];
        __syncthreads();
    }
    int offset = spart[0];
    if (i < NN) {
        int r = s[tid] - v + offset;
        g_rowptr[i] = r;
        g_cur[i] = r;
    }
    if (bid == NBLK - 1 && tid == 511) g_rowptr[NN] = NE;
}

// ---------------- fill CSR: 4 edges/thread, NO dinv loads --------------------
__global__ void k_fill4(const int* __restrict__ src, const int* __restrict__ dst,
                        const float* __restrict__ ew) {
    int i = blockIdx.x * 256 + threadIdx.x;
    if (i < NE / 4) {
        int4   s = ((const int4*)src)[i];
        int4   d = ((const int4*)dst)[i];
        float4 w = ((const float4*)ew)[i];
        int p0 = atomicAdd(&g_cur[d.x], 1);
        int p1 = atomicAdd(&g_cur[d.y], 1);
        int p2 = atomicAdd(&g_cur[d.z], 1);
        int p3 = atomicAdd(&g_cur[d.w], 1);
        g_edge[p0] = make_int2(s.x, __float_as_int(w.x));
        g_edge[p1] = make_int2(s.y, __float_as_int(w.y));
        g_edge[p2] = make_int2(s.z, __float_as_int(w.z));
        g_edge[p3] = make_int2(s.w, __float_as_int(w.w));
    }
}

// ---------------- agg, 1 float4/thread (layer-1, WID=8) ---------------------
template <int WID>
__global__ void k_agg(const float* __restrict__ h, float* __restrict__ out) {
    constexpr int G = WID / 4;
    int idx = blockIdx.x * 256 + threadIdx.x;
    int node = idx / G, g = idx % G;
    if (node >= NN) return;

    int beg = g_rowptr[node];
    int end = g_rowptr[node + 1];
    float d = g_dinv[node];

    const float4* h4 = (const float4*)h;
    float4 acc = h4[(size_t)node * G + g];

    int e = beg;
    for (; e + 2 <= end; e += 2) {
        int2 ed0 = g_edge[e];
        int2 ed1 = g_edge[e + 1];
        float4 v0 = h4[(size_t)ed0.x * G + g];
        float4 v1 = h4[(size_t)ed1.x * G + g];
        float n0 = __int_as_float(ed0.y);
        float n1 = __int_as_float(ed1.y);
        acc.x += n0 * v0.x; acc.y += n0 * v0.y;
        acc.z += n0 * v0.z; acc.w += n0 * v0.w;
        acc.x += n1 * v1.x; acc.y += n1 * v1.y;
        acc.z += n1 * v1.z; acc.w += n1 * v1.w;
    }
    if (e < end) {
        int2 ed = g_edge[e];
        float n = __int_as_float(ed.y);
        float4 v = h4[(size_t)ed.x * G + g];
        acc.x += n * v.x; acc.y += n * v.y;
        acc.z += n * v.z; acc.w += n * v.w;
    }
    ((float4*)out)[(size_t)node * G + g] =
        make_float4(acc.x * d, acc.y * d, acc.z * d, acc.w * d);
}

// ---------------- agg, 4 strided float4s/thread (WID=32/128) ----------------
// G = WID/16 threads per node; thread g owns float4s g, g+G, g+2G, g+3G.
// Unroll-2 edge loop => 8 independent 16B gathers in flight per thread.
template <int WID>
__global__ void k_agg4(const float* __restrict__ h, float* __restrict__ out) {
    constexpr int G  = WID / 16;           // threads per node
    constexpr int F4 = WID / 4;            // float4s per node row
    int idx = blockIdx.x * 256 + threadIdx.x;
    int node = idx / G, g = idx % G;
    if (node >= NN) return;

    int beg = g_rowptr[node];
    int end = g_rowptr[node + 1];
    float d = g_dinv[node];

    const float4* h4 = (const float4*)h;
    size_t base = (size_t)node * F4;
    float4 acc[4];
#pragma unroll
    for (int j = 0; j < 4; j++) acc[j] = h4[base + g + j * G];

    int e = beg;
    for (; e + 2 <= end; e += 2) {
        int2 ed0 = g_edge[e];
        int2 ed1 = g_edge[e + 1];
        size_t b0 = (size_t)ed0.x * F4;
        size_t b1 = (size_t)ed1.x * F4;
        float4 v0[4], v1[4];
#pragma unroll
        for (int j = 0; j < 4; j++) v0[j] = h4[b0 + g + j * G];
#pragma unroll
        for (int j = 0; j < 4; j++) v1[j] = h4[b1 + g + j * G];
        float n0 = __int_as_float(ed0.y);
        float n1 = __int_as_float(ed1.y);
#pragma unroll
        for (int j = 0; j < 4; j++) {
            acc[j].x += n0 * v0[j].x; acc[j].y += n0 * v0[j].y;
            acc[j].z += n0 * v0[j].z; acc[j].w += n0 * v0[j].w;
            acc[j].x += n1 * v1[j].x; acc[j].y += n1 * v1[j].y;
            acc[j].z += n1 * v1[j].z; acc[j].w += n1 * v1[j].w;
        }
    }
    if (e < end) {
        int2 ed = g_edge[e];
        float n = __int_as_float(ed.y);
        size_t b0 = (size_t)ed.x * F4;
#pragma unroll
        for (int j = 0; j < 4; j++) {
            float4 v = h4[b0 + g + j * G];
            acc[j].x += n * v.x; acc[j].y += n * v.y;
            acc[j].z += n * v.z; acc[j].w += n * v.w;
        }
    }
#pragma unroll
    for (int j = 0; j < 4; j++)
        ((float4*)out)[base + g + j * G] =
            make_float4(acc[j].x * d, acc[j].y * d, acc[j].z * d, acc[j].w * d);
}

// ---------------- tensor-core GEMM: Hout = [relu](X @ W [+ b]) [* dinv] ------
template <int K, int N, bool BIAS, bool RELU, bool SCALEOUT>
__global__ void __launch_bounds__(256) k_mma(const float* __restrict__ X,
                                             const __nv_bfloat16* __restrict__ wHi,
                                             const __nv_bfloat16* __restrict__ wLo,
                                             const float* __restrict__ bias,
                                             float* __restrict__ Hout) {
    constexpr int SK  = K + 8;
    constexpr int NT  = N / 8;
    constexpr int NKC = K / 16;
    extern __shared__ __nv_bfloat16 sb[];
    __nv_bfloat16* sHi = sb;
    __nv_bfloat16* sLo = sb + N * SK;

    int tid = threadIdx.x, wid = tid >> 5, lane = tid & 31;

    for (int i = tid; i < N * (K / 2); i += 256) {
        int n = i / (K / 2), k = (i % (K / 2)) * 2;
        *(uint32_t*)&sHi[n * SK + k] = ((const uint32_t*)wHi)[(n * K + k) >> 1];
        *(uint32_t*)&sLo[n * SK + k] = ((const uint32_t*)wLo)[(n * K + k) >> 1];
    }
    __syncthreads();

    int grp = lane >> 2;
    int qk  = (lane & 3) * 2;
    int l8   = lane & 7;
    int koff = ((lane >> 3) & 1) * 8;
    uint32_t bHiBase = smem_u32(sHi) + (uint32_t)((l8 * SK + koff) * 2);
    uint32_t bLoBase = smem_u32(sLo) + (uint32_t)((l8 * SK + koff) * 2);

    constexpr int NTILES = (NN + 127) / 128;
    for (int t = blockIdx.x; t < NTILES; t += gridDim.x) {
        int rbase = t * 128 + wid * 16;
        int r0 = rbase + grp;
        int r8 = r0 + 8;
        const float* x0 = X + (size_t)(r0 < NN ? r0 : NN - 1) * K;
        const float* x8 = X + (size_t)(r8 < NN ? r8 : NN - 1) * K;

        float acc[NT][4];
#pragma unroll
        for (int nt = 0; nt < NT; nt++)
#pragma unroll
            for (int j = 0; j < 4; j++) acc[nt][j] = 0.0f;

#pragma unroll
        for (int kc = 0; kc < NKC; kc++) {
            int k = kc * 16 + qk;
            float2 f0 = *(const float2*)(x0 + k);
            float2 f1 = *(const float2*)(x8 + k);
            float2 f2 = *(const float2*)(x0 + k + 8);
            float2 f3 = *(const float2*)(x8 + k + 8);
            uint32_t aHi[4], aLo[4];
            cvt2(f0, aHi[0], aLo[0]);
            cvt2(f1, aHi[1], aLo[1]);
            cvt2(f2, aHi[2], aLo[2]);
            cvt2(f3, aHi[3], aLo[3]);

#pragma unroll
            for (int nt = 0; nt < NT; nt++) {
                uint32_t off = (uint32_t)(nt * 8 * SK * 2 + kc * 32);
                uint32_t bHi[2], bLo[2];
                ldmx2(bHi, bHiBase + off);
                ldmx2(bLo, bLoBase + off);
                mma16816(acc[nt], aHi, bHi);
                mma16816(acc[nt], aHi, bLo);
                mma16816(acc[nt], aLo, bHi);
            }
        }

        bool ok0 = r0 < NN, ok8 = r8 < NN;
        float dr0 = 1.0f, dr8 = 1.0f;
        if (SCALEOUT) {
            dr0 = g_dinv[r0 < NN ? r0 : NN - 1];
            dr8 = g_dinv[r8 < NN ? r8 : NN - 1];
        }
#pragma unroll
        for (int nt = 0; nt < NT; nt++) {
            int col = nt * 8 + qk;
            float2 v0 = make_float2(acc[nt][0], acc[nt][1]);
            float2 v1 = make_float2(acc[nt][2], acc[nt][3]);
            if (BIAS) {
                float2 bv = *(const float2*)(bias + col);
                v0.x += bv.x; v0.y += bv.y;
                v1.x += bv.x; v1.y += bv.y;
            }
            if (RELU) {
                v0.x = fmaxf(v0.x, 0.f); v0.y = fmaxf(v0.y, 0.f);
                v1.x = fmaxf(v1.x, 0.f); v1.y = fmaxf(v1.y, 0.f);
            }
            if (SCALEOUT) {
                v0.x *= dr0; v0.y *= dr0;
                v1.x *= dr8; v1.y *= dr8;
            }
            if (ok0) *(float2*)(Hout + (size_t)r0 * N + col) = v0;
            if (ok8) *(float2*)(Hout + (size_t)r8 * N + col) = v1;
        }
    }
}

constexpr int mma_smem(int K, int N) { return 2 * N * (K + 8) * 2; }

// ---------------- FUSED layers 3+4: out = (relu(X@W3+b3) @ W4) * dinv -------
__global__ void __launch_bounds__(256) k_mma34(const float* __restrict__ X,
                                               const float* __restrict__ bias3,
                                               float* __restrict__ Hout) {
    constexpr int K = 128, SK = 136;
    extern __shared__ __nv_bfloat16 sb[];
    __nv_bfloat16* sHi3 = sb;                       // [128][136]
    __nv_bfloat16* sLo3 = sHi3 + 128 * SK;
    __nv_bfloat16* sHi4 = sLo3 + 128 * SK;          // [32][136]
    __nv_bfloat16* sLo4 = sHi4 + 32 * SK;

    int tid = threadIdx.x, wid = tid >> 5, lane = tid & 31;

    for (int i = tid; i < 128 * 64; i += 256) {
        int n = i >> 6, k = (i & 63) * 2;
        *(uint32_t*)&sHi3[n * SK + k] = ((const uint32_t*)g_wHi3)[(n * 128 + k) >> 1];
        *(uint32_t*)&sLo3[n * SK + k] = ((const uint32_t*)g_wLo3)[(n * 128 + k) >> 1];
    }
    for (int i = tid; i < 32 * 64; i += 256) {
        int n = i >> 6, k = (i & 63) * 2;
        *(uint32_t*)&sHi4[n * SK + k] = ((const uint32_t*)g_wHi4)[(n * 128 + k) >> 1];
        *(uint32_t*)&sLo4[n * SK + k] = ((const uint32_t*)g_wLo4)[(n * 128 + k) >> 1];
    }
    __syncthreads();

    int grp = lane >> 2;
    int qk  = (lane & 3) * 2;
    int l8   = lane & 7;
    int koff = ((lane >> 3) & 1) * 8;
    uint32_t b3Hi = smem_u32(sHi3) + (uint32_t)((l8 * SK + koff) * 2);
    uint32_t b3Lo = smem_u32(sLo3) + (uint32_t)((l8 * SK + koff) * 2);
    uint32_t b4Hi = smem_u32(sHi4) + (uint32_t)((l8 * SK + koff) * 2);
    uint32_t b4Lo = smem_u32(sLo4) + (uint32_t)((l8 * SK + koff) * 2);

    constexpr int NTILES = (NN + 127) / 128;
    for (int t = blockIdx.x; t < NTILES; t += gridDim.x) {
        int rbase = t * 128 + wid * 16;
        int r0 = rbase + grp;
        int r8 = r0 + 8;
        const float* x0 = X + (size_t)(r0 < NN ? r0 : NN - 1) * K;
        const float* x8 = X + (size_t)(r8 < NN ? r8 : NN - 1) * K;

        float acc[16][4];
#pragma unroll
        for (int nt = 0; nt < 16; nt++)
#pragma unroll
            for (int j = 0; j < 4; j++) acc[nt][j] = 0.0f;

#pragma unroll
        for (int kc = 0; kc < 8; kc++) {
            int k = kc * 16 + qk;
            float2 f0 = *(const float2*)(x0 + k);
            float2 f1 = *(const float2*)(x8 + k);
            float2 f2 = *(const float2*)(x0 + k + 8);
            float2 f3 = *(const float2*)(x8 + k + 8);
            uint32_t aHi[4], aLo[4];
            cvt2(f0, aHi[0], aLo[0]);
            cvt2(f1, aHi[1], aLo[1]);
            cvt2(f2, aHi[2], aLo[2]);
            cvt2(f3, aHi[3], aLo[3]);

#pragma unroll
            for (int nt = 0; nt < 16; nt++) {
                uint32_t off = (uint32_t)(nt * 8 * SK * 2 + kc * 32);
                uint32_t bHi[2], bLo[2];
                ldmx2(bHi, b3Hi + off);
                ldmx2(bLo, b3Lo + off);
                mma16816(acc[nt], aHi, bHi);
                mma16816(acc[nt], aHi, bLo);
                mma16816(acc[nt], aLo, bHi);
            }
        }

#pragma unroll
        for (int nt = 0; nt < 16; nt++) {
            int col = nt * 8 + qk;
            float2 bv = *(const float2*)(bias3 + col);
            acc[nt][0] = fmaxf(acc[nt][0] + bv.x, 0.f);
            acc[nt][1] = fmaxf(acc[nt][1] + bv.y, 0.f);
            acc[nt][2] = fmaxf(acc[nt][2] + bv.x, 0.f);
            acc[nt][3] = fmaxf(acc[nt][3] + bv.y, 0.f);
        }

        float acc2[4][4];
#pragma unroll
        for (int nt = 0; nt < 4; nt++)
#pragma unroll
            for (int j = 0; j < 4; j++) acc2[nt][j] = 0.0f;

#pragma unroll
        for (int kc = 0; kc < 8; kc++) {
            uint32_t aHi[4], aLo[4];
            cvt2(make_float2(acc[2 * kc][0],     acc[2 * kc][1]),     aHi[0], aLo[0]);
            cvt2(make_float2(acc[2 * kc][2],     acc[2 * kc][3]),     aHi[1], aLo[1]);
            cvt2(make_float2(acc[2 * kc + 1][0], acc[2 * kc + 1][1]), aHi[2], aLo[2]);
            cvt2(make_float2(acc[2 * kc + 1][2], acc[2 * kc + 1][3]), aHi[3], aLo[3]);

#pragma unroll
            for (int nt = 0; nt < 4; nt++) {
                uint32_t off = (uint32_t)(nt * 8 * SK * 2 + kc * 32);
                uint32_t bHi[2], bLo[2];
                ldmx2(bHi, b4Hi + off);
                ldmx2(bLo, b4Lo + off);
                mma16816(acc2[nt], aHi, bHi);
                mma16816(acc2[nt], aHi, bLo);
                mma16816(acc2[nt], aLo, bHi);
            }
        }

        bool ok0 = r0 < NN, ok8 = r8 < NN;
        float dr0 = g_dinv[r0 < NN ? r0 : NN - 1];
        float dr8 = g_dinv[r8 < NN ? r8 : NN - 1];
#pragma unroll
        for (int nt = 0; nt < 4; nt++) {
            int col = nt * 8 + qk;
            if (ok0) *(float2*)(Hout + (size_t)r0 * 32 + col) =
                make_float2(acc2[nt][0] * dr0, acc2[nt][1] * dr0);
            if (ok8) *(float2*)(Hout + (size_t)r8 * 32 + col) =
                make_float2(acc2[nt][2] * dr8, acc2[nt][3] * dr8);
        }
    }
}

constexpr int SM_M34 = 2 * 128 * 136 * 2 + 2 * 32 * 136 * 2;   // 87,040 B

// ---------------- layer-4: agg then relu(acc*dinv + b4), segment-max --------
__global__ void k_aggsegmax(const float* __restrict__ h, const float* __restrict__ b,
                            unsigned* __restrict__ outmax) {
    int tid = threadIdx.x;
    int lane = tid & 31;
    int idx = blockIdx.x * 256 + tid;
    int node = idx >> 3, g = idx & 7;
    float4 acc = make_float4(0.f, 0.f, 0.f, 0.f);
    if (node < NN) {
        float d = g_dinv[node];
        const float4* h4 = (const float4*)h;
        float4 bv = ((const float4*)b)[g];
        acc = h4[(size_t)node * 8 + g];
        int beg = g_rowptr[node], end = g_rowptr[node + 1];
        int e = beg;
        for (; e + 2 <= end; e += 2) {
            int2 ed0 = g_edge[e];
            int2 ed1 = g_edge[e + 1];
            float4 v0 = h4[(size_t)ed0.x * 8 + g];
            float4 v1 = h4[(size_t)ed1.x * 8 + g];
            float n0 = __int_as_float(ed0.y);
            float n1 = __int_as_float(ed1.y);
            acc.x += n0 * v0.x; acc.y += n0 * v0.y;
            acc.z += n0 * v0.z; acc.w += n0 * v0.w;
            acc.x += n1 * v1.x; acc.y += n1 * v1.y;
            acc.z += n1 * v1.z; acc.w += n1 * v1.w;
        }
        if (e < end) {
            int2 ed = g_edge[e];
            float n = __int_as_float(ed.y);
            float4 v = h4[(size_t)ed.x * 8 + g];
            acc.x += n * v.x; acc.y += n * v.y;
            acc.z += n * v.z; acc.w += n * v.w;
        }
        acc.x = fmaxf(acc.x * d + bv.x, 0.f);
        acc.y = fmaxf(acc.y * d + bv.y, 0.f);
        acc.z = fmaxf(acc.z * d + bv.z, 0.f);
        acc.w = fmaxf(acc.w * d + bv.w, 0.f);
    }
#pragma unroll
    for (int off = 8; off < 32; off <<= 1) {
        acc.x = fmaxf(acc.x, __shfl_xor_sync(0xffffffffu, acc.x, off));
        acc.y = fmaxf(acc.y, __shfl_xor_sync(0xffffffffu, acc.y, off));
        acc.z = fmaxf(acc.z, __shfl_xor_sync(0xffffffffu, acc.z, off));
        acc.w = fmaxf(acc.w, __shfl_xor_sync(0xffffffffu, acc.w, off));
    }
    __shared__ float4 sm[8][8];          // [warp][g]
    if (lane < 8) sm[tid >> 5][lane] = acc;
    __syncthreads();
    if (tid < 8) {
        float4 m = sm[0][tid];
#pragma unroll
        for (int w = 1; w < 8; w++) {
            float4 o = sm[w][tid];
            m.x = fmaxf(m.x, o.x); m.y = fmaxf(m.y, o.y);
            m.z = fmaxf(m.z, o.z); m.w = fmaxf(m.w, o.w);
        }
        atomicMax(&outmax[tid * 4 + 0], __float_as_uint(m.x));
        atomicMax(&outmax[tid * 4 + 1], __float_as_uint(m.y));
        atomicMax(&outmax[tid * 4 + 2], __float_as_uint(m.z));
        atomicMax(&outmax[tid * 4 + 3], __float_as_uint(m.w));
    }
}

// ---------------- FFMA GEMM layer 1 (8 -> 32) + segmax + scaled store -------
template <int IN, int OUT>
__global__ void __launch_bounds__(256) k_gemm1(const float* __restrict__ X,
                                               const float* __restrict__ W,
                                               const float* __restrict__ b,
                                               float* __restrict__ H,
                                               unsigned* __restrict__ outmax) {
    constexpr int K4 = IN / 4;
    constexpr int ROWS = 64;
    __shared__ float sW[IN * OUT];
    __shared__ float sX[ROWS * IN];
    __shared__ float smax[256];
    int tid = threadIdx.x;
    int tx = tid & 31, ty = tid >> 5;

    for (int i = tid; i < IN * OUT / 4; i += 256)
        ((float4*)sW)[i] = ((const float4*)W)[i];
    float bv = b[tx];
    __syncthreads();

    float mval = 0.0f;
    const int ntiles = (NN + ROWS - 1) / ROWS;
    for (int t = blockIdx.x; t < ntiles; t += gridDim.x) {
        int rbase = t * ROWS;
        for (int i = tid; i < ROWS * K4; i += 256) {
            int r = i / K4;
            float4 v = make_float4(0.f, 0.f, 0.f, 0.f);
            if (rbase + r < NN) v = ((const float4*)X)[(size_t)(rbase + r) * K4 + (i % K4)];
            ((float4*)sX)[i] = v;
        }
        __syncthreads();

        float acc[8];
#pragma unroll
        for (int rr = 0; rr < 8; rr++) acc[rr] = 0.0f;

#pragma unroll
        for (int k4 = 0; k4 < K4; k4++) {
            float4 xr[8];
#pragma unroll
            for (int rr = 0; rr < 8; rr++)
                xr[rr] = ((float4*)sX)[(ty * 8 + rr) * K4 + k4];
#pragma unroll
            for (int kk = 0; kk < 4; kk++) {
                float wv = sW[(k4 * 4 + kk) * 32 + tx];
#pragma unroll
                for (int rr = 0; rr < 8; rr++)
                    acc[rr] += ((const float*)&xr[rr])[kk] * wv;
            }
        }

#pragma unroll
        for (int rr = 0; rr < 8; rr++) {
            int row = rbase + ty * 8 + rr;
            if (row < NN) {
                float v = fmaxf(acc[rr] + bv, 0.0f);
                H[(size_t)row * 32 + tx] = v * g_dinv[row];   // scaled store
                mval = fmaxf(mval, v);                        // max on unscaled
            }
        }
        __syncthreads();
    }

    smax[tid] = mval;
    __syncthreads();
    if (ty == 0) {
#pragma unroll
        for (int w = 1; w < 8; w++) mval = fmaxf(mval, smax[w * 32 + tx]);
        atomicMax(&outmax[tx], __float_as_uint(mval));
    }
}

// ---------------- MLP head + softmax + code write ---------------------------
__global__ void k_head(const float* __restrict__ C2ER,
                       const unsigned* __restrict__ x0, const unsigned* __restrict__ x1,
                       const float* __restrict__ L1W, const float* __restrict__ L1b,
                       const float* __restrict__ L2W, const float* __restrict__ L2b,
                       const float* __restrict__ L3W, const float* __restrict__ L3b,
                       float* __restrict__ out) {
    __shared__ float code[68], z1[128], z2[128], logits[10];
    int t = threadIdx.x;
    if (t < 32)       code[t] = __uint_as_float(x0[t]);
    else if (t < 64)  code[t] = __uint_as_float(x1[t - 32]);
    else if (t < 68)  code[t] = C2ER[t - 64];
    __syncthreads();

    float a = L1b[t];
#pragma unroll
    for (int i = 0; i < 68; i++) a += code[i] * L1W[i * 128 + t];
    z1[t] = fmaxf(a, 0.0f);
    __syncthreads();

    a = L2b[t];
#pragma unroll
    for (int i = 0; i < 128; i++) a += z1[i] * L2W[i * 128 + t];
    z2[t] = fmaxf(a, 0.0f);
    __syncthreads();

    if (t < 10) {
        float s = L3b[t];
#pragma unroll
        for (int i = 0; i < 128; i++) s += z2[i] * L3W[i * 10 + t];
        logits[t] = s;
    }
    __syncthreads();

    if (t == 0) {
        float mx = -1e30f;
        for (int j = 0; j < 10; j++) mx = fmaxf(mx, logits[j]);
        float e[10], sum = 0.0f;
        for (int j = 0; j < 10; j++) { e[j] = expf(logits[j] - mx); sum += e[j]; }
        float inv = 1.0f / sum;
        for (int j = 0; j < 10; j++) out[j] = e[j] * inv;
        for (int j = 0; j < 68; j++) out[10 + j] = code[j];
    }
}

// ---------------- launch ----------------------------------------------------
extern "C" void kernel_launch(void* const* d_in, const int* in_sizes, int n_in,
                              void* d_out, int out_size) {
    const float* x    = (const float*)d_in[0];
    const int*   ei   = (const int*)d_in[1];
    const float* ew   = (const float*)d_in[2];
    const float* C2ER = (const float*)d_in[4];
    const float* W1 = (const float*)d_in[5],  *b1 = (const float*)d_in[6];
    const float* W2 = (const float*)d_in[7],  *b2 = (const float*)d_in[8];
    const float* W3 = (const float*)d_in[9],  *b3 = (const float*)d_in[10];
    const float* W4 = (const float*)d_in[11], *b4 = (const float*)d_in[12];
    const float* L1W = (const float*)d_in[13], *L1b = (const float*)d_in[14];
    const float* L2W = (const float*)d_in[15], *L2b = (const float*)d_in[16];
    const float* L3W = (const float*)d_in[17], *L3b = (const float*)d_in[18];
    float* out = (float*)d_out;

    const int* src = ei;
    const int* dst = ei + NE;

    void *pH, *pA, *pB, *px0, *px1, *pwHi2, *pwLo2;
    cudaGetSymbolAddress(&pH, g_bufH);
    cudaGetSymbolAddress(&pA, g_bufA);
    cudaGetSymbolAddress(&pB, g_bufB);
    cudaGetSymbolAddress(&px0, g_x0);
    cudaGetSymbolAddress(&px1, g_x1);
    cudaGetSymbolAddress(&pwHi2, g_wHi2);
    cudaGetSymbolAddress(&pwLo2, g_wLo2);
    float* H = (float*)pH;
    float* A = (float*)pA;
    float* B = (float*)pB;

    constexpr int SM_M2 = mma_smem(32, 128);    // 20,480 B
    cudaFuncSetAttribute(k_mma34,
                         cudaFuncAttributeMaxDynamicSharedMemorySize, SM_M34);

    // ---- init + weight conversion (one kernel) ----
    k_wconv_init<<<(NN + 255) / 256, 256>>>(W2, W3, W4);

    // ---- CSR build: packed degree (x4) -> scan (+dinv, +x prescale) -> fill -
    k_deg4  <<<(NE / 4 + 255) / 256, 256>>>(dst, ew);
    k_scan  <<<NBLK, 512>>>(x, B);              // B holds xs = x * dinv
    k_fill4 <<<(NE / 4 + 255) / 256, 256>>>(src, dst, ew);

    // ---- Layer 1: agg(xs)[8] -> GEMM 8->32 (+b1, relu, segmax, *dinv) -> A --
    k_agg<8><<<(NN * 2 + 255) / 256, 256>>>(B, H);
    k_gemm1<8, 32><<<592, 256>>>(H, W1, b1, A, (unsigned*)px0);

    // ---- Layer 2: agg4(h1')[32] -> MMA 32->128 (+b2, relu, *dinv) -> B ----
    k_agg4<32><<<(NN * 2 + 255) / 256, 256>>>(A, H);
    k_mma<32, 128, true, true, true><<<296, 256, SM_M2>>>(
        H, (const __nv_bfloat16*)pwHi2, (const __nv_bfloat16*)pwLo2, b2, B);

    // ---- Layers 3+4 fused: agg4(h2')[128] -> (relu(X@W3+b3)@W4)*dinv -> A ----
    k_agg4<128><<<(NN * 8 + 255) / 256, 256>>>(B, H);
    k_mma34<<<296, 256, SM_M34>>>(H, b3, A);

    // ---- layer-4 agg -> relu(acc*dinv+b4) -> segmax x1 ----
    k_aggsegmax<<<(NN * 8 + 255) / 256, 256>>>(A, b4, (unsigned*)px1);

    // ---- Head ----
    k_head<<<1, 128>>>(C2ER, (const unsigned*)px0, (const unsigned*)px1,
                       L1W, L1b, L2W, L2b, L3W, L3b, out);
}

// round 17
// speedup vs baseline: 1.0285x; 1.0285x over previous
#include <cuda_runtime.h>
#include <cuda_bf16.h>
#include <cstdint>

#define NN 100000
#define NE 600000
#define NBLK 196   // ceil(NN/512) scan blocks

// ---------------- scratch (device globals; no allocation allowed) ----------
__device__ float    g_bufH[(size_t)NN * 128];
__device__ float    g_bufA[(size_t)NN * 128];
__device__ float    g_bufB[(size_t)NN * 128];
__device__ float    g_dinv[NN];
__device__ unsigned long long g_pack[NN];    // count<<40 | fixpoint(weight, 2^16)
__device__ int      g_rowptr[NN + 1];
__device__ int      g_cur[NN];
__device__ int2     g_edge[NE];              // {src, float-bits(ew)}
__device__ unsigned g_x0[32];
__device__ unsigned g_x1[32];
__device__ unsigned long long g_pub[NBLK];   // lookback: flag(bit32) | sum
__device__ __align__(16) __nv_bfloat16 g_wHi2[32 * 128];
__device__ __align__(16) __nv_bfloat16 g_wLo2[32 * 128];
__device__ __align__(16) __nv_bfloat16 g_wHi3[128 * 128];
__device__ __align__(16) __nv_bfloat16 g_wLo3[128 * 128];
__device__ __align__(16) __nv_bfloat16 g_wHi4[128 * 32];
__device__ __align__(16) __nv_bfloat16 g_wLo4[128 * 32];

// ======================= mma.sync helpers ===================================
__device__ __forceinline__ uint32_t smem_u32(const void* p) {
    uint32_t a;
    asm("{ .reg .u64 t; cvta.to.shared.u64 t, %1; cvt.u32.u64 %0, t; }"
        : "=r"(a) : "l"(p));
    return a;
}

__device__ __forceinline__ void ldmx2(uint32_t* r, uint32_t addr) {
    asm volatile("ldmatrix.sync.aligned.m8n8.x2.shared.b16 {%0,%1}, [%2];"
                 : "=r"(r[0]), "=r"(r[1]) : "r"(addr));
}

__device__ __forceinline__ void mma16816(float* c, const uint32_t* a, const uint32_t* b) {
    asm volatile(
        "mma.sync.aligned.m16n8k16.row.col.f32.bf16.bf16.f32 "
        "{%0,%1,%2,%3}, {%4,%5,%6,%7}, {%8,%9}, {%0,%1,%2,%3};"
        : "+f"(c[0]), "+f"(c[1]), "+f"(c[2]), "+f"(c[3])
        : "r"(a[0]), "r"(a[1]), "r"(a[2]), "r"(a[3]), "r"(b[0]), "r"(b[1]));
}

__device__ __forceinline__ void cvt2(float2 f, uint32_t& hi, uint32_t& lo) {
    __nv_bfloat162 h = __floats2bfloat162_rn(f.x, f.y);
    float2 hf = __bfloat1622float2(h);
    __nv_bfloat162 l = __floats2bfloat162_rn(f.x - hf.x, f.y - hf.y);
    hi = *(uint32_t*)&h;
    lo = *(uint32_t*)&l;
}

__device__ __forceinline__ void cvt_hilo(float x, unsigned short& h, unsigned short& l) {
    __nv_bfloat16 hb = __float2bfloat16(x);
    __nv_bfloat16 lb = __float2bfloat16(x - __bfloat162float(hb));
    h = __bfloat16_as_ushort(hb);
    l = __bfloat16_as_ushort(lb);
}

// ---------------- init + weight convert (one kernel) ------------------------
__global__ void k_wconv_init(const float* __restrict__ W2,
                             const float* __restrict__ W3,
                             const float* __restrict__ W4) {
    int i = blockIdx.x * 256 + threadIdx.x;
    if (i < NN) g_pack[i] = 65536ULL;   // self-loop weight 1.0 (2^16), count 0
    if (i < 32) { g_x0[i] = 0u; g_x1[i] = 0u; }
    if (i < NBLK) g_pub[i] = 0ULL;
    unsigned short h, l;
    if (i < 4096) {                                   // W2: K=32, N=128
        int n = i >> 5, k = i & 31;
        cvt_hilo(W2[k * 128 + n], h, l);
        g_wHi2[i] = __ushort_as_bfloat16(h);
        g_wLo2[i] = __ushort_as_bfloat16(l);
    } else if (i < 4096 + 16384) {                    // W3: K=128, N=128
        int j = i - 4096;
        int n = j >> 7, k = j & 127;
        cvt_hilo(W3[k * 128 + n], h, l);
        g_wHi3[j] = __ushort_as_bfloat16(h);
        g_wLo3[j] = __ushort_as_bfloat16(l);
    } else if (i < 4096 + 16384 + 4096) {             // W4: K=128, N=32
        int j = i - 20480;
        int n = j >> 7, k = j & 127;
        cvt_hilo(W4[k * 32 + n], h, l);
        g_wHi4[j] = __ushort_as_bfloat16(h);
        g_wLo4[j] = __ushort_as_bfloat16(l);
    }
}

// ---------------- degree: 4 edges/thread, ONE packed atomic per edge --------
__global__ void k_deg4(const int* __restrict__ dst, const float* __restrict__ ew) {
    int i = blockIdx.x * 256 + threadIdx.x;
    if (i < NE / 4) {
        int4   d = ((const int4*)dst)[i];
        float4 w = ((const float4*)ew)[i];
        const unsigned long long ONE = 1ULL << 40;
        atomicAdd(&g_pack[d.x], ONE + (unsigned long long)__float2uint_rn(w.x * 65536.0f));
        atomicAdd(&g_pack[d.y], ONE + (unsigned long long)__float2uint_rn(w.y * 65536.0f));
        atomicAdd(&g_pack[d.z], ONE + (unsigned long long)__float2uint_rn(w.z * 65536.0f));
        atomicAdd(&g_pack[d.w], ONE + (unsigned long long)__float2uint_rn(w.w * 65536.0f));
    }
}

// ---------------- single-kernel exclusive scan + dinv + x prescale ----------
__global__ void __launch_bounds__(512) k_scan(const float* __restrict__ x,
                                              float* __restrict__ xs) {
    __shared__ int s[512];
    __shared__ int spart[512];
    int tid = threadIdx.x, bid = blockIdx.x;
    int i = bid * 512 + tid;
    int v = 0;
    if (i < NN) {
        unsigned long long p = g_pack[i];
        v = (int)(p >> 40);
        float d = rsqrtf((float)(p & 0xFFFFFFFFFFULL) * (1.0f / 65536.0f));
        g_dinv[i] = d;
        float4 a = ((const float4*)x)[i * 2];
        float4 b = ((const float4*)x)[i * 2 + 1];
        a.x *= d; a.y *= d; a.z *= d; a.w *= d;
        b.x *= d; b.y *= d; b.z *= d; b.w *= d;
        ((float4*)xs)[i * 2]     = a;
        ((float4*)xs)[i * 2 + 1] = b;
    }
    s[tid] = v;
    __syncthreads();
#pragma unroll
    for (int off = 1; off < 512; off <<= 1) {
        int t = 0;
        if (tid >= off) t = s[tid - off];
        __syncthreads();
        if (tid >= off) s[tid] += t;
        __syncthreads();
    }
    if (tid == 511)
        atomicExch(&g_pub[bid], (1ULL << 32) | (unsigned long long)(unsigned)s[511]);

    int part = 0;
    for (int j = tid; j < bid; j += 512) {
        unsigned long long p;
        do { p = atomicAdd(&g_pub[j], 0ULL); } while ((p >> 32) == 0ULL);
        part += (int)(p & 0xffffffffULL);
    }
    spart[tid] = part;
    __syncthreads();
#pragma unroll
    for (int ssz = 256; ssz > 0; ssz >>= 1) {
        if (tid < ssz) spart[tid] += spart[tid + ssz];
        __syncthreads();
    }
    int offset = spart[0];
    if (i < NN) {
        int r = s[tid] - v + offset;
        g_rowptr[i] = r;
        g_cur[i] = r;
    }
    if (bid == NBLK - 1 && tid == 511) g_rowptr[NN] = NE;
}

// ---------------- fill CSR: 4 edges/thread, NO dinv loads --------------------
__global__ void k_fill4(const int* __restrict__ src, const int* __restrict__ dst,
                        const float* __restrict__ ew) {
    int i = blockIdx.x * 256 + threadIdx.x;
    if (i < NE / 4) {
        int4   s = ((const int4*)src)[i];
        int4   d = ((const int4*)dst)[i];
        float4 w = ((const float4*)ew)[i];
        int p0 = atomicAdd(&g_cur[d.x], 1);
        int p1 = atomicAdd(&g_cur[d.y], 1);
        int p2 = atomicAdd(&g_cur[d.z], 1);
        int p3 = atomicAdd(&g_cur[d.w], 1);
        g_edge[p0] = make_int2(s.x, __float_as_int(w.x));
        g_edge[p1] = make_int2(s.y, __float_as_int(w.y));
        g_edge[p2] = make_int2(s.z, __float_as_int(w.z));
        g_edge[p3] = make_int2(s.w, __float_as_int(w.w));
    }
}

// ---------------- agg, 1 float4/thread (layer-1, WID=8) ---------------------
template <int WID>
__global__ void k_agg(const float* __restrict__ h, float* __restrict__ out) {
    constexpr int G = WID / 4;
    int idx = blockIdx.x * 256 + threadIdx.x;
    int node = idx / G, g = idx % G;
    if (node >= NN) return;

    int beg = g_rowptr[node];
    int end = g_rowptr[node + 1];
    float d = g_dinv[node];

    const float4* h4 = (const float4*)h;
    float4 acc = h4[(size_t)node * G + g];

    int e = beg;
    for (; e + 2 <= end; e += 2) {
        int2 ed0 = g_edge[e];
        int2 ed1 = g_edge[e + 1];
        float4 v0 = h4[(size_t)ed0.x * G + g];
        float4 v1 = h4[(size_t)ed1.x * G + g];
        float n0 = __int_as_float(ed0.y);
        float n1 = __int_as_float(ed1.y);
        acc.x += n0 * v0.x; acc.y += n0 * v0.y;
        acc.z += n0 * v0.z; acc.w += n0 * v0.w;
        acc.x += n1 * v1.x; acc.y += n1 * v1.y;
        acc.z += n1 * v1.z; acc.w += n1 * v1.w;
    }
    if (e < end) {
        int2 ed = g_edge[e];
        float n = __int_as_float(ed.y);
        float4 v = h4[(size_t)ed.x * G + g];
        acc.x += n * v.x; acc.y += n * v.y;
        acc.z += n * v.z; acc.w += n * v.w;
    }
    ((float4*)out)[(size_t)node * G + g] =
        make_float4(acc.x * d, acc.y * d, acc.z * d, acc.w * d);
}

// ---------------- agg, 2 strided float4s/thread, edge loop unroll-4 ---------
// G threads per node; thread g owns float4s g and g+G. Unroll-4 edge loop =>
// 8 independent 16B gathers + 4 edge loads in flight per thread.
template <int WID>
__global__ void k_agg2(const float* __restrict__ h, float* __restrict__ out) {
    constexpr int G = WID / 8;             // thread groups per node
    int idx = blockIdx.x * 256 + threadIdx.x;
    int node = idx / G, g = idx % G;
    if (node >= NN) return;

    int beg = g_rowptr[node];
    int end = g_rowptr[node + 1];
    float d = g_dinv[node];

    const float4* h4 = (const float4*)h;
    size_t base = (size_t)node * (2 * G);
    float4 acc0 = h4[base + g];
    float4 acc1 = h4[base + g + G];

    int e = beg;
    for (; e + 4 <= end; e += 4) {
        int2 ed0 = g_edge[e];
        int2 ed1 = g_edge[e + 1];
        int2 ed2 = g_edge[e + 2];
        int2 ed3 = g_edge[e + 3];
        size_t b0 = (size_t)ed0.x * (2 * G);
        size_t b1 = (size_t)ed1.x * (2 * G);
        size_t b2 = (size_t)ed2.x * (2 * G);
        size_t b3 = (size_t)ed3.x * (2 * G);
        float4 v00 = h4[b0 + g], v01 = h4[b0 + g + G];
        float4 v10 = h4[b1 + g], v11 = h4[b1 + g + G];
        float4 v20 = h4[b2 + g], v21 = h4[b2 + g + G];
        float4 v30 = h4[b3 + g], v31 = h4[b3 + g + G];
        float n0 = __int_as_float(ed0.y);
        float n1 = __int_as_float(ed1.y);
        float n2 = __int_as_float(ed2.y);
        float n3 = __int_as_float(ed3.y);
        acc0.x += n0 * v00.x; acc0.y += n0 * v00.y;
        acc0.z += n0 * v00.z; acc0.w += n0 * v00.w;
        acc1.x += n0 * v01.x; acc1.y += n0 * v01.y;
        acc1.z += n0 * v01.z; acc1.w += n0 * v01.w;
        acc0.x += n1 * v10.x; acc0.y += n1 * v10.y;
        acc0.z += n1 * v10.z; acc0.w += n1 * v10.w;
        acc1.x += n1 * v11.x; acc1.y += n1 * v11.y;
        acc1.z += n1 * v11.z; acc1.w += n1 * v11.w;
        acc0.x += n2 * v20.x; acc0.y += n2 * v20.y;
        acc0.z += n2 * v20.z; acc0.w += n2 * v20.w;
        acc1.x += n2 * v21.x; acc1.y += n2 * v21.y;
        acc1.z += n2 * v21.z; acc1.w += n2 * v21.w;
        acc0.x += n3 * v30.x; acc0.y += n3 * v30.y;
        acc0.z += n3 * v30.z; acc0.w += n3 * v30.w;
        acc1.x += n3 * v31.x; acc1.y += n3 * v31.y;
        acc1.z += n3 * v31.z; acc1.w += n3 * v31.w;
    }
    for (; e + 2 <= end; e += 2) {
        int2 ed0 = g_edge[e];
        int2 ed1 = g_edge[e + 1];
        size_t b0 = (size_t)ed0.x * (2 * G);
        size_t b1 = (size_t)ed1.x * (2 * G);
        float4 v00 = h4[b0 + g], v01 = h4[b0 + g + G];
        float4 v10 = h4[b1 + g], v11 = h4[b1 + g + G];
        float n0 = __int_as_float(ed0.y);
        float n1 = __int_as_float(ed1.y);
        acc0.x += n0 * v00.x; acc0.y += n0 * v00.y;
        acc0.z += n0 * v00.z; acc0.w += n0 * v00.w;
        acc1.x += n0 * v01.x; acc1.y += n0 * v01.y;
        acc1.z += n0 * v01.z; acc1.w += n0 * v01.w;
        acc0.x += n1 * v10.x; acc0.y += n1 * v10.y;
        acc0.z += n1 * v10.z; acc0.w += n1 * v10.w;
        acc1.x += n1 * v11.x; acc1.y += n1 * v11.y;
        acc1.z += n1 * v11.z; acc1.w += n1 * v11.w;
    }
    if (e < end) {
        int2 ed = g_edge[e];
        float n = __int_as_float(ed.y);
        size_t b0 = (size_t)ed.x * (2 * G);
        float4 v0 = h4[b0 + g];
        float4 v1 = h4[b0 + g + G];
        acc0.x += n * v0.x; acc0.y += n * v0.y;
        acc0.z += n * v0.z; acc0.w += n * v0.w;
        acc1.x += n * v1.x; acc1.y += n * v1.y;
        acc1.z += n * v1.z; acc1.w += n * v1.w;
    }
    ((float4*)out)[base + g] =
        make_float4(acc0.x * d, acc0.y * d, acc0.z * d, acc0.w * d);
    ((float4*)out)[base + g + G] =
        make_float4(acc1.x * d, acc1.y * d, acc1.z * d, acc1.w * d);
}

// ---------------- tensor-core GEMM: Hout = [relu](X @ W [+ b]) [* dinv] ------
template <int K, int N, bool BIAS, bool RELU, bool SCALEOUT>
__global__ void __launch_bounds__(256) k_mma(const float* __restrict__ X,
                                             const __nv_bfloat16* __restrict__ wHi,
                                             const __nv_bfloat16* __restrict__ wLo,
                                             const float* __restrict__ bias,
                                             float* __restrict__ Hout) {
    constexpr int SK  = K + 8;
    constexpr int NT  = N / 8;
    constexpr int NKC = K / 16;
    extern __shared__ __nv_bfloat16 sb[];
    __nv_bfloat16* sHi = sb;
    __nv_bfloat16* sLo = sb + N * SK;

    int tid = threadIdx.x, wid = tid >> 5, lane = tid & 31;

    for (int i = tid; i < N * (K / 2); i += 256) {
        int n = i / (K / 2), k = (i % (K / 2)) * 2;
        *(uint32_t*)&sHi[n * SK + k] = ((const uint32_t*)wHi)[(n * K + k) >> 1];
        *(uint32_t*)&sLo[n * SK + k] = ((const uint32_t*)wLo)[(n * K + k) >> 1];
    }
    __syncthreads();

    int grp = lane >> 2;
    int qk  = (lane & 3) * 2;
    int l8   = lane & 7;
    int koff = ((lane >> 3) & 1) * 8;
    uint32_t bHiBase = smem_u32(sHi) + (uint32_t)((l8 * SK + koff) * 2);
    uint32_t bLoBase = smem_u32(sLo) + (uint32_t)((l8 * SK + koff) * 2);

    constexpr int NTILES = (NN + 127) / 128;
    for (int t = blockIdx.x; t < NTILES; t += gridDim.x) {
        int rbase = t * 128 + wid * 16;
        int r0 = rbase + grp;
        int r8 = r0 + 8;
        const float* x0 = X + (size_t)(r0 < NN ? r0 : NN - 1) * K;
        const float* x8 = X + (size_t)(r8 < NN ? r8 : NN - 1) * K;

        float acc[NT][4];
#pragma unroll
        for (int nt = 0; nt < NT; nt++)
#pragma unroll
            for (int j = 0; j < 4; j++) acc[nt][j] = 0.0f;

#pragma unroll
        for (int kc = 0; kc < NKC; kc++) {
            int k = kc * 16 + qk;
            float2 f0 = *(const float2*)(x0 + k);
            float2 f1 = *(const float2*)(x8 + k);
            float2 f2 = *(const float2*)(x0 + k + 8);
            float2 f3 = *(const float2*)(x8 + k + 8);
            uint32_t aHi[4], aLo[4];
            cvt2(f0, aHi[0], aLo[0]);
            cvt2(f1, aHi[1], aLo[1]);
            cvt2(f2, aHi[2], aLo[2]);
            cvt2(f3, aHi[3], aLo[3]);

#pragma unroll
            for (int nt = 0; nt < NT; nt++) {
                uint32_t off = (uint32_t)(nt * 8 * SK * 2 + kc * 32);
                uint32_t bHi[2], bLo[2];
                ldmx2(bHi, bHiBase + off);
                ldmx2(bLo, bLoBase + off);
                mma16816(acc[nt], aHi, bHi);
                mma16816(acc[nt], aHi, bLo);
                mma16816(acc[nt], aLo, bHi);
            }
        }

        bool ok0 = r0 < NN, ok8 = r8 < NN;
        float dr0 = 1.0f, dr8 = 1.0f;
        if (SCALEOUT) {
            dr0 = g_dinv[r0 < NN ? r0 : NN - 1];
            dr8 = g_dinv[r8 < NN ? r8 : NN - 1];
        }
#pragma unroll
        for (int nt = 0; nt < NT; nt++) {
            int col = nt * 8 + qk;
            float2 v0 = make_float2(acc[nt][0], acc[nt][1]);
            float2 v1 = make_float2(acc[nt][2], acc[nt][3]);
            if (BIAS) {
                float2 bv = *(const float2*)(bias + col);
                v0.x += bv.x; v0.y += bv.y;
                v1.x += bv.x; v1.y += bv.y;
            }
            if (RELU) {
                v0.x = fmaxf(v0.x, 0.f); v0.y = fmaxf(v0.y, 0.f);
                v1.x = fmaxf(v1.x, 0.f); v1.y = fmaxf(v1.y, 0.f);
            }
            if (SCALEOUT) {
                v0.x *= dr0; v0.y *= dr0;
                v1.x *= dr8; v1.y *= dr8;
            }
            if (ok0) *(float2*)(Hout + (size_t)r0 * N + col) = v0;
            if (ok8) *(float2*)(Hout + (size_t)r8 * N + col) = v1;
        }
    }
}

constexpr int mma_smem(int K, int N) { return 2 * N * (K + 8) * 2; }

// ---------------- FUSED layers 3+4: out = (relu(X@W3+b3) @ W4) * dinv -------
__global__ void __launch_bounds__(256) k_mma34(const float* __restrict__ X,
                                               const float* __restrict__ bias3,
                                               float* __restrict__ Hout) {
    constexpr int K = 128, SK = 136;
    extern __shared__ __nv_bfloat16 sb[];
    __nv_bfloat16* sHi3 = sb;                       // [128][136]
    __nv_bfloat16* sLo3 = sHi3 + 128 * SK;
    __nv_bfloat16* sHi4 = sLo3 + 128 * SK;          // [32][136]
    __nv_bfloat16* sLo4 = sHi4 + 32 * SK;

    int tid = threadIdx.x, wid = tid >> 5, lane = tid & 31;

    for (int i = tid; i < 128 * 64; i += 256) {
        int n = i >> 6, k = (i & 63) * 2;
        *(uint32_t*)&sHi3[n * SK + k] = ((const uint32_t*)g_wHi3)[(n * 128 + k) >> 1];
        *(uint32_t*)&sLo3[n * SK + k] = ((const uint32_t*)g_wLo3)[(n * 128 + k) >> 1];
    }
    for (int i = tid; i < 32 * 64; i += 256) {
        int n = i >> 6, k = (i & 63) * 2;
        *(uint32_t*)&sHi4[n * SK + k] = ((const uint32_t*)g_wHi4)[(n * 128 + k) >> 1];
        *(uint32_t*)&sLo4[n * SK + k] = ((const uint32_t*)g_wLo4)[(n * 128 + k) >> 1];
    }
    __syncthreads();

    int grp = lane >> 2;
    int qk  = (lane & 3) * 2;
    int l8   = lane & 7;
    int koff = ((lane >> 3) & 1) * 8;
    uint32_t b3Hi = smem_u32(sHi3) + (uint32_t)((l8 * SK + koff) * 2);
    uint32_t b3Lo = smem_u32(sLo3) + (uint32_t)((l8 * SK + koff) * 2);
    uint32_t b4Hi = smem_u32(sHi4) + (uint32_t)((l8 * SK + koff) * 2);
    uint32_t b4Lo = smem_u32(sLo4) + (uint32_t)((l8 * SK + koff) * 2);

    constexpr int NTILES = (NN + 127) / 128;
    for (int t = blockIdx.x; t < NTILES; t += gridDim.x) {
        int rbase = t * 128 + wid * 16;
        int r0 = rbase + grp;
        int r8 = r0 + 8;
        const float* x0 = X + (size_t)(r0 < NN ? r0 : NN - 1) * K;
        const float* x8 = X + (size_t)(r8 < NN ? r8 : NN - 1) * K;

        float acc[16][4];
#pragma unroll
        for (int nt = 0; nt < 16; nt++)
#pragma unroll
            for (int j = 0; j < 4; j++) acc[nt][j] = 0.0f;

#pragma unroll
        for (int kc = 0; kc < 8; kc++) {
            int k = kc * 16 + qk;
            float2 f0 = *(const float2*)(x0 + k);
            float2 f1 = *(const float2*)(x8 + k);
            float2 f2 = *(const float2*)(x0 + k + 8);
            float2 f3 = *(const float2*)(x8 + k + 8);
            uint32_t aHi[4], aLo[4];
            cvt2(f0, aHi[0], aLo[0]);
            cvt2(f1, aHi[1], aLo[1]);
            cvt2(f2, aHi[2], aLo[2]);
            cvt2(f3, aHi[3], aLo[3]);

#pragma unroll
            for (int nt = 0; nt < 16; nt++) {
                uint32_t off = (uint32_t)(nt * 8 * SK * 2 + kc * 32);
                uint32_t bHi[2], bLo[2];
                ldmx2(bHi, b3Hi + off);
                ldmx2(bLo, b3Lo + off);
                mma16816(acc[nt], aHi, bHi);
                mma16816(acc[nt], aHi, bLo);
                mma16816(acc[nt], aLo, bHi);
            }
        }

#pragma unroll
        for (int nt = 0; nt < 16; nt++) {
            int col = nt * 8 + qk;
            float2 bv = *(const float2*)(bias3 + col);
            acc[nt][0] = fmaxf(acc[nt][0] + bv.x, 0.f);
            acc[nt][1] = fmaxf(acc[nt][1] + bv.y, 0.f);
            acc[nt][2] = fmaxf(acc[nt][2] + bv.x, 0.f);
            acc[nt][3] = fmaxf(acc[nt][3] + bv.y, 0.f);
        }

        float acc2[4][4];
#pragma unroll
        for (int nt = 0; nt < 4; nt++)
#pragma unroll
            for (int j = 0; j < 4; j++) acc2[nt][j] = 0.0f;

#pragma unroll
        for (int kc = 0; kc < 8; kc++) {
            uint32_t aHi[4], aLo[4];
            cvt2(make_float2(acc[2 * kc][0],     acc[2 * kc][1]),     aHi[0], aLo[0]);
            cvt2(make_float2(acc[2 * kc][2],     acc[2 * kc][3]),     aHi[1], aLo[1]);
            cvt2(make_float2(acc[2 * kc + 1][0], acc[2 * kc + 1][1]), aHi[2], aLo[2]);
            cvt2(make_float2(acc[2 * kc + 1][2], acc[2 * kc + 1][3]), aHi[3], aLo[3]);

#pragma unroll
            for (int nt = 0; nt < 4; nt++) {
                uint32_t off = (uint32_t)(nt * 8 * SK * 2 + kc * 32);
                uint32_t bHi[2], bLo[2];
                ldmx2(bHi, b4Hi + off);
                ldmx2(bLo, b4Lo + off);
                mma16816(acc2[nt], aHi, bHi);
                mma16816(acc2[nt], aHi, bLo);
                mma16816(acc2[nt], aLo, bHi);
            }
        }

        bool ok0 = r0 < NN, ok8 = r8 < NN;
        float dr0 = g_dinv[r0 < NN ? r0 : NN - 1];
        float dr8 = g_dinv[r8 < NN ? r8 : NN - 1];
#pragma unroll
        for (int nt = 0; nt < 4; nt++) {
            int col = nt * 8 + qk;
            if (ok0) *(float2*)(Hout + (size_t)r0 * 32 + col) =
                make_float2(acc2[nt][0] * dr0, acc2[nt][1] * dr0);
            if (ok8) *(float2*)(Hout + (size_t)r8 * 32 + col) =
                make_float2(acc2[nt][2] * dr8, acc2[nt][3] * dr8);
        }
    }
}

constexpr int SM_M34 = 2 * 128 * 136 * 2 + 2 * 32 * 136 * 2;   // 87,040 B

// ---------------- layer-4: agg then relu(acc*dinv + b4), segment-max --------
__global__ void k_aggsegmax(const float* __restrict__ h, const float* __restrict__ b,
                            unsigned* __restrict__ outmax) {
    int tid = threadIdx.x;
    int lane = tid & 31;
    int idx = blockIdx.x * 256 + tid;
    int node = idx >> 3, g = idx & 7;
    float4 acc = make_float4(0.f, 0.f, 0.f, 0.f);
    if (node < NN) {
        float d = g_dinv[node];
        const float4* h4 = (const float4*)h;
        float4 bv = ((const float4*)b)[g];
        acc = h4[(size_t)node * 8 + g];
        int beg = g_rowptr[node], end = g_rowptr[node + 1];
        int e = beg;
        for (; e + 2 <= end; e += 2) {
            int2 ed0 = g_edge[e];
            int2 ed1 = g_edge[e + 1];
            float4 v0 = h4[(size_t)ed0.x * 8 + g];
            float4 v1 = h4[(size_t)ed1.x * 8 + g];
            float n0 = __int_as_float(ed0.y);
            float n1 = __int_as_float(ed1.y);
            acc.x += n0 * v0.x; acc.y += n0 * v0.y;
            acc.z += n0 * v0.z; acc.w += n0 * v0.w;
            acc.x += n1 * v1.x; acc.y += n1 * v1.y;
            acc.z += n1 * v1.z; acc.w += n1 * v1.w;
        }
        if (e < end) {
            int2 ed = g_edge[e];
            float n = __int_as_float(ed.y);
            float4 v = h4[(size_t)ed.x * 8 + g];
            acc.x += n * v.x; acc.y += n * v.y;
            acc.z += n * v.z; acc.w += n * v.w;
        }
        acc.x = fmaxf(acc.x * d + bv.x, 0.f);
        acc.y = fmaxf(acc.y * d + bv.y, 0.f);
        acc.z = fmaxf(acc.z * d + bv.z, 0.f);
        acc.w = fmaxf(acc.w * d + bv.w, 0.f);
    }
#pragma unroll
    for (int off = 8; off < 32; off <<= 1) {
        acc.x = fmaxf(acc.x, __shfl_xor_sync(0xffffffffu, acc.x, off));
        acc.y = fmaxf(acc.y, __shfl_xor_sync(0xffffffffu, acc.y, off));
        acc.z = fmaxf(acc.z, __shfl_xor_sync(0xffffffffu, acc.z, off));
        acc.w = fmaxf(acc.w, __shfl_xor_sync(0xffffffffu, acc.w, off));
    }
    __shared__ float4 sm[8][8];          // [warp][g]
    if (lane < 8) sm[tid >> 5][lane] = acc;
    __syncthreads();
    if (tid < 8) {
        float4 m = sm[0][tid];
#pragma unroll
        for (int w = 1; w < 8; w++) {
            float4 o = sm[w][tid];
            m.x = fmaxf(m.x, o.x); m.y = fmaxf(m.y, o.y);
            m.z = fmaxf(m.z, o.z); m.w = fmaxf(m.w, o.w);
        }
        atomicMax(&outmax[tid * 4 + 0], __float_as_uint(m.x));
        atomicMax(&outmax[tid * 4 + 1], __float_as_uint(m.y));
        atomicMax(&outmax[tid * 4 + 2], __float_as_uint(m.z));
        atomicMax(&outmax[tid * 4 + 3], __float_as_uint(m.w));
    }
}

// ---------------- FFMA GEMM layer 1 (8 -> 32) + segmax + scaled store -------
template <int IN, int OUT>
__global__ void __launch_bounds__(256) k_gemm1(const float* __restrict__ X,
                                               const float* __restrict__ W,
                                               const float* __restrict__ b,
                                               float* __restrict__ H,
                                               unsigned* __restrict__ outmax) {
    constexpr int K4 = IN / 4;
    constexpr int ROWS = 64;
    __shared__ float sW[IN * OUT];
    __shared__ float sX[ROWS * IN];
    __shared__ float smax[256];
    int tid = threadIdx.x;
    int tx = tid & 31, ty = tid >> 5;

    for (int i = tid; i < IN * OUT / 4; i += 256)
        ((float4*)sW)[i] = ((const float4*)W)[i];
    float bv = b[tx];
    __syncthreads();

    float mval = 0.0f;
    const int ntiles = (NN + ROWS - 1) / ROWS;
    for (int t = blockIdx.x; t < ntiles; t += gridDim.x) {
        int rbase = t * ROWS;
        for (int i = tid; i < ROWS * K4; i += 256) {
            int r = i / K4;
            float4 v = make_float4(0.f, 0.f, 0.f, 0.f);
            if (rbase + r < NN) v = ((const float4*)X)[(size_t)(rbase + r) * K4 + (i % K4)];
            ((float4*)sX)[i] = v;
        }
        __syncthreads();

        float acc[8];
#pragma unroll
        for (int rr = 0; rr < 8; rr++) acc[rr] = 0.0f;

#pragma unroll
        for (int k4 = 0; k4 < K4; k4++) {
            float4 xr[8];
#pragma unroll
            for (int rr = 0; rr < 8; rr++)
                xr[rr] = ((float4*)sX)[(ty * 8 + rr) * K4 + k4];
#pragma unroll
            for (int kk = 0; kk < 4; kk++) {
                float wv = sW[(k4 * 4 + kk) * 32 + tx];
#pragma unroll
                for (int rr = 0; rr < 8; rr++)
                    acc[rr] += ((const float*)&xr[rr])[kk] * wv;
            }
        }

#pragma unroll
        for (int rr = 0; rr < 8; rr++) {
            int row = rbase + ty * 8 + rr;
            if (row < NN) {
                float v = fmaxf(acc[rr] + bv, 0.0f);
                H[(size_t)row * 32 + tx] = v * g_dinv[row];   // scaled store
                mval = fmaxf(mval, v);                        // max on unscaled
            }
        }
        __syncthreads();
    }

    smax[tid] = mval;
    __syncthreads();
    if (ty == 0) {
#pragma unroll
        for (int w = 1; w < 8; w++) mval = fmaxf(mval, smax[w * 32 + tx]);
        atomicMax(&outmax[tx], __float_as_uint(mval));
    }
}

// ---------------- MLP head + softmax + code write ---------------------------
__global__ void k_head(const float* __restrict__ C2ER,
                       const unsigned* __restrict__ x0, const unsigned* __restrict__ x1,
                       const float* __restrict__ L1W, const float* __restrict__ L1b,
                       const float* __restrict__ L2W, const float* __restrict__ L2b,
                       const float* __restrict__ L3W, const float* __restrict__ L3b,
                       float* __restrict__ out) {
    __shared__ float code[68], z1[128], z2[128], logits[10];
    int t = threadIdx.x;
    if (t < 32)       code[t] = __uint_as_float(x0[t]);
    else if (t < 64)  code[t] = __uint_as_float(x1[t - 32]);
    else if (t < 68)  code[t] = C2ER[t - 64];
    __syncthreads();

    float a = L1b[t];
#pragma unroll
    for (int i = 0; i < 68; i++) a += code[i] * L1W[i * 128 + t];
    z1[t] = fmaxf(a, 0.0f);
    __syncthreads();

    a = L2b[t];
#pragma unroll
    for (int i = 0; i < 128; i++) a += z1[i] * L2W[i * 128 + t];
    z2[t] = fmaxf(a, 0.0f);
    __syncthreads();

    if (t < 10) {
        float s = L3b[t];
#pragma unroll
        for (int i = 0; i < 128; i++) s += z2[i] * L3W[i * 10 + t];
        logits[t] = s;
    }
    __syncthreads();

    if (t == 0) {
        float mx = -1e30f;
        for (int j = 0; j < 10; j++) mx = fmaxf(mx, logits[j]);
        float e[10], sum = 0.0f;
        for (int j = 0; j < 10; j++) { e[j] = expf(logits[j] - mx); sum += e[j]; }
        float inv = 1.0f / sum;
        for (int j = 0; j < 10; j++) out[j] = e[j] * inv;
        for (int j = 0; j < 68; j++) out[10 + j] = code[j];
    }
}

// ---------------- launch ----------------------------------------------------
extern "C" void kernel_launch(void* const* d_in, const int* in_sizes, int n_in,
                              void* d_out, int out_size) {
    const float* x    = (const float*)d_in[0];
    const int*   ei   = (const int*)d_in[1];
    const float* ew   = (const float*)d_in[2];
    const float* C2ER = (const float*)d_in[4];
    const float* W1 = (const float*)d_in[5],  *b1 = (const float*)d_in[6];
    const float* W2 = (const float*)d_in[7],  *b2 = (const float*)d_in[8];
    const float* W3 = (const float*)d_in[9],  *b3 = (const float*)d_in[10];
    const float* W4 = (const float*)d_in[11], *b4 = (const float*)d_in[12];
    const float* L1W = (const float*)d_in[13], *L1b = (const float*)d_in[14];
    const float* L2W = (const float*)d_in[15], *L2b = (const float*)d_in[16];
    const float* L3W = (const float*)d_in[17], *L3b = (const float*)d_in[18];
    float* out = (float*)d_out;

    const int* src = ei;
    const int* dst = ei + NE;

    void *pH, *pA, *pB, *px0, *px1, *pwHi2, *pwLo2;
    cudaGetSymbolAddress(&pH, g_bufH);
    cudaGetSymbolAddress(&pA, g_bufA);
    cudaGetSymbolAddress(&pB, g_bufB);
    cudaGetSymbolAddress(&px0, g_x0);
    cudaGetSymbolAddress(&px1, g_x1);
    cudaGetSymbolAddress(&pwHi2, g_wHi2);
    cudaGetSymbolAddress(&pwLo2, g_wLo2);
    float* H = (float*)pH;
    float* A = (float*)pA;
    float* B = (float*)pB;

    constexpr int SM_M2 = mma_smem(32, 128);    // 20,480 B
    cudaFuncSetAttribute(k_mma34,
                         cudaFuncAttributeMaxDynamicSharedMemorySize, SM_M34);

    // ---- init + weight conversion (one kernel) ----
    k_wconv_init<<<(NN + 255) / 256, 256>>>(W2, W3, W4);

    // ---- CSR build: packed degree (x4) -> scan (+dinv, +x prescale) -> fill -
    k_deg4  <<<(NE / 4 + 255) / 256, 256>>>(dst, ew);
    k_scan  <<<NBLK, 512>>>(x, B);              // B holds xs = x * dinv
    k_fill4 <<<(NE / 4 + 255) / 256, 256>>>(src, dst, ew);

    // ---- Layer 1: agg(xs)[8] -> GEMM 8->32 (+b1, relu, segmax, *dinv) -> A --
    k_agg<8><<<(NN * 2 + 255) / 256, 256>>>(B, H);
    k_gemm1<8, 32><<<592, 256>>>(H, W1, b1, A, (unsigned*)px0);

    // ---- Layer 2: agg2(h1')[32] -> MMA 32->128 (+b2, relu, *dinv) -> B ----
    k_agg2<32><<<(NN * 4 + 255) / 256, 256>>>(A, H);
    k_mma<32, 128, true, true, true><<<296, 256, SM_M2>>>(
        H, (const __nv_bfloat16*)pwHi2, (const __nv_bfloat16*)pwLo2, b2, B);

    // ---- Layers 3+4 fused: agg2(h2')[128] -> (relu(X@W3+b3)@W4)*dinv -> A ----
    k_agg2<128><<<(NN * 16 + 255) / 256, 256>>>(B, H);
    k_mma34<<<296, 256, SM_M34>>>(H, b3, A);

    // ---- layer-4 agg -> relu(acc*dinv+b4) -> segmax x1 ----
    k_aggsegmax<<<(NN * 8 + 255) / 256, 256>>>(A, b4, (unsigned*)px1);

    // ---- Head ----
    k_head<<<1, 128>>>(C2ER, (const unsigned*)px0, (const unsigned*)px1,
                       L1W, L1b, L2W, L2b, L3W, L3b, out);
}